// round 15
// baseline (speedup 1.0000x reference)
#include <cuda_runtime.h>
#include <cuda_bf16.h>

// Persistent 2-layer tanh RNN, sm_103 tensor cores (mma.sync bf16 x3).
// R15 = R14 (15.24ms: 128 CTAs, 128x128 tiles, 8-way split-K, in-stage merge,
// 2 barriers/step, fc folded via M0, batched output GEMM) + ONE change:
// W-hi limbs RESIDENT in smem (64KB per stage per CTA, loaded once) -> per
// chunk stages only {Ah, Al, Wl}. Cuts ~16MB/step of L2 traffic (the model:
// remaining wall is L2 bandwidth; barriers/latency/warps all tested null).

typedef unsigned long long u64;
typedef unsigned int u32;

namespace {
constexpr int NCTA = 128;
constexpr int NTHR = 256;
constexpr int Bm = 256, Hd = 1024, Ind = 256, Tt = 512;
constexpr int BmHd = Bm * Hd;
constexpr int TILE_F = 128 * 128;
// smem layout:
//  [0,64K)      RW_A: resident W-hi for stage A (4 chunks x 16KB)
//  [64K,128K)   RW_B: resident W-hi for stage B
//  [128K,176K)  BUF0: {Ah,Al,Wl} 3x16KB     [176K,224K) BUF1
//  full-staging path (phase0b / finalGEMM) reuses [0,128K) as 2x64KB buffers
constexpr u32 RW_A = 0, RW_B = 65536;
constexpr u32 BUF0 = 131072, BUF1 = 180224;
constexpr u32 B_AH = 0, B_AL = 16384, B_WL = 32768;
constexpr u32 F_AH = 0, F_AL = 16384, F_WH = 32768, F_WL = 49152;
constexpr int SMEM_BYTES = 229376;  // 224KB <= 227KB cap
}

// ---- device-global state (allocation-free rule) ----
__device__ __align__(16) __nv_bfloat16 g_Wih0h[Hd * Ind], g_Wih0l[Hd * Ind];
__device__ __align__(16) __nv_bfloat16 g_Whh0h[Hd * Hd],  g_Whh0l[Hd * Hd];
__device__ __align__(16) __nv_bfloat16 g_Wih1h[Hd * Hd],  g_Wih1l[Hd * Hd];
__device__ __align__(16) __nv_bfloat16 g_Whh1h[Hd * Hd],  g_Whh1l[Hd * Hd];
__device__ __align__(16) __nv_bfloat16 g_M0h[Hd * Hd],    g_M0l[Hd * Hd];
__device__ __align__(16) __nv_bfloat16 g_fcWh[Ind * Hd],  g_fcWl[Ind * Hd];
__device__ __align__(16) __nv_bfloat16 g_fcWTh[Hd * Ind], g_fcWTl[Hd * Ind];
__device__ __align__(16) __nv_bfloat16 g_yh[Bm * Ind],    g_yl[Bm * Ind];
__device__ __align__(16) __nv_bfloat16 g_h0h[2][BmHd],    g_h0l[2][BmHd];
__device__ __align__(16) __nv_bfloat16 g_H1h[Tt * BmHd],  g_H1l[Tt * BmHd];
__device__ float g_biasA1[Hd], g_biasAf[Hd], g_biasB[Hd];
__device__ float g_part[16 * 8 * TILE_F];
__device__ u32 g_tcnt[16];
__device__ unsigned g_arrive = 0, g_gen = 0;

// ---- helpers ----
__device__ __forceinline__ u32 smem_u32(const void *p) {
    u32 a;
    asm("{ .reg .u64 t; cvta.to.shared.u64 t, %1; cvt.u32.u64 %0, t; }"
        : "=r"(a) : "l"(p));
    return a;
}

#define LDMX4(r, a) \
    asm volatile("ldmatrix.sync.aligned.m8n8.x4.shared.b16 {%0,%1,%2,%3}, [%4];" \
                 : "=r"((r)[0]), "=r"((r)[1]), "=r"((r)[2]), "=r"((r)[3]) : "r"(a))

__device__ __forceinline__ void mma16816(float *c, const u32 *a, u32 b0, u32 b1) {
    asm volatile(
        "mma.sync.aligned.m16n8k16.row.col.f32.bf16.bf16.f32 "
        "{%0,%1,%2,%3}, {%4,%5,%6,%7}, {%8,%9}, {%0,%1,%2,%3};"
        : "+f"(c[0]), "+f"(c[1]), "+f"(c[2]), "+f"(c[3])
        : "r"(a[0]), "r"(a[1]), "r"(a[2]), "r"(a[3]), "r"(b0), "r"(b1));
}

__device__ __forceinline__ void commitg() {
    asm volatile("cp.async.commit_group;" ::: "memory");
}
__device__ __forceinline__ void waitg0() {
    asm volatile("cp.async.wait_group 0;" ::: "memory");
}
__device__ __forceinline__ void waitg1() {
    asm volatile("cp.async.wait_group 1;" ::: "memory");
}

// ---- grid barrier (validated R4-R14) ----
__device__ __forceinline__ void grid_sync() {
    __syncthreads();
    if (threadIdx.x == 0) {
        unsigned gen = *(volatile unsigned *)&g_gen;
        __threadfence();
        if (atomicAdd(&g_arrive, 1u) == NCTA - 1) {
            atomicExch(&g_arrive, 0u);
            __threadfence();
            atomicAdd(&g_gen, 1u);
        } else {
            while (*(volatile unsigned *)&g_gen == gen) { }
            __threadfence();
        }
    }
    __syncthreads();
}

// per-tile sub-barrier (validated R14)
__device__ __forceinline__ void tile_sync(int tile, bool produce, u32 target) {
    __syncthreads();
    if (threadIdx.x == 0) {
        if (produce) {
            __threadfence();
            atomicAdd(&g_tcnt[tile], 1u);
        }
        while (*(volatile u32 *)&g_tcnt[tile] < target) { }
        __threadfence();
    }
    __syncthreads();
}

__device__ __forceinline__ void split_bf16(float v, __nv_bfloat16 &h, __nv_bfloat16 &l) {
    h = __float2bfloat16(v);
    l = __float2bfloat16(v - __bfloat162float(h));
}

// cp.async one 128x64 bf16 tile (SW128 xor swizzle) into smem.
__device__ __forceinline__ void stage_async(u32 sdst, const __nv_bfloat16 *g,
                                            int ld, int kb) {
    const int tid = threadIdx.x;
#pragma unroll
    for (int j = 0; j < 4; ++j) {
        const int u = tid + NTHR * j;
        const int row = u >> 3, blk = u & 7;
        const size_t src = __cvta_generic_to_global(&g[(long)row * ld + kb + blk * 8]);
        const u32 dst = sdst + row * 128 + ((blk ^ (row & 7)) << 4);
        asm volatile("cp.async.cg.shared.global [%0], [%1], 16;"
                     :: "r"(dst), "l"(src) : "memory");
    }
}

// resident-path chunk: stage {Ah, Al, Wl} only
__device__ __forceinline__ void issue_res(
    u32 buf, const __nv_bfloat16 *Ah, const __nv_bfloat16 *Al, int lda,
    const __nv_bfloat16 *Wl, int ldw, int kb) {
    stage_async(buf + B_AH, Ah, lda, kb);
    stage_async(buf + B_AL, Al, lda, kb);
    stage_async(buf + B_WL, Wl, ldw, kb);
    commitg();
}

// full-staging chunk (phase0b / final GEMM)
__device__ __forceinline__ void issue_full(
    u32 buf, const __nv_bfloat16 *Ah, const __nv_bfloat16 *Al, int lda,
    const __nv_bfloat16 *Wh, const __nv_bfloat16 *Wl, int ldw, int kb) {
    stage_async(buf + F_AH, Ah, lda, kb);
    stage_async(buf + F_AL, Al, lda, kb);
    stage_async(buf + F_WH, Wh, ldw, kb);
    stage_async(buf + F_WL, Wl, ldw, kb);
    commitg();
}

// MMA over one staged 64-k chunk; explicit smem addresses for the 4 operand
// tiles. 8 warps as 2x4; warp tile 64x32. Math identical to R8-R14.
__device__ __forceinline__ void mma_tile(float (&acc)[4][4][4],
                                         u32 aH, u32 aL, u32 wH, u32 wL) {
    const int lid = threadIdx.x & 31, wid = threadIdx.x >> 5;
    const int wm = wid >> 2, wn = wid & 3;
    const int rA0 = wm * 64 + (lid & 7) + ((lid >> 3) & 1) * 8;
    const int cAsel = (lid >> 4) & 1;
    const int rB0 = wn * 32 + (lid & 7) + ((lid >> 4) & 1) * 8;
    const int cBsel = (lid >> 3) & 1;
#pragma unroll
    for (int k16 = 0; k16 < 4; ++k16) {
        u32 ah[4][4], al[4][4], bh[2][4], bl[2][4];
#pragma unroll
        for (int ma = 0; ma < 4; ++ma) {
            const int r = rA0 + ma * 16;
            const u32 off = (u32)(r * 128 + (((k16 * 2 + cAsel) ^ (r & 7)) << 4));
            LDMX4(ah[ma], aH + off);
            LDMX4(al[ma], aL + off);
        }
#pragma unroll
        for (int p = 0; p < 2; ++p) {
            const int r = rB0 + p * 16;
            const u32 off = (u32)(r * 128 + (((k16 * 2 + cBsel) ^ (r & 7)) << 4));
            LDMX4(bh[p], wH + off);
            LDMX4(bl[p], wL + off);
        }
#pragma unroll
        for (int ma = 0; ma < 4; ++ma)
#pragma unroll
            for (int na = 0; na < 4; ++na) {
                const int p = na >> 1, q = (na & 1) * 2;
                mma16816(acc[ma][na], ah[ma], bh[p][q], bh[p][q + 1]);
                mma16816(acc[ma][na], ah[ma], bl[p][q], bl[p][q + 1]);
                mma16816(acc[ma][na], al[ma], bh[p][q], bh[p][q + 1]);
            }
    }
}

// Pipelined GEMM with resident W-hi (nch chunks; resident chunk i at rw+i*16K).
__device__ __forceinline__ void gemm_res(
    float (&acc)[4][4][4], u32 sb,
    const __nv_bfloat16 *Ah, const __nv_bfloat16 *Al, int lda,
    const __nv_bfloat16 *Wl, int ldw, u32 rw, int kb, int nch)
{
    issue_res(sb + BUF0, Ah, Al, lda, Wl, ldw, kb);
    if (nch > 1) issue_res(sb + BUF1, Ah, Al, lda, Wl, ldw, kb + 64);
    for (int i = 0; i < nch; ++i) {
        if (i + 1 < nch) waitg1(); else waitg0();
        __syncthreads();
        const u32 buf = sb + ((i & 1) ? BUF1 : BUF0);
        mma_tile(acc, buf + B_AH, buf + B_AL, sb + rw + (u32)i * 16384u, buf + B_WL);
        __syncthreads();
        if (i + 2 < nch)
            issue_res(sb + ((i & 1) ? BUF1 : BUF0), Ah, Al, lda, Wl, ldw,
                      kb + 64 * (i + 2));
    }
}

// Full-staging pipelined GEMM (phase0b / final GEMM), buffers at [base, base+128K).
__device__ __forceinline__ void gemm_full(
    float (&acc)[4][4][4], u32 sb, u32 base,
    const __nv_bfloat16 *Ah, const __nv_bfloat16 *Al, int lda,
    const __nv_bfloat16 *Wh, const __nv_bfloat16 *Wl, int ldw,
    int kb, int nch)
{
    issue_full(sb + base, Ah, Al, lda, Wh, Wl, ldw, kb);
    if (nch > 1) issue_full(sb + base + 65536, Ah, Al, lda, Wh, Wl, ldw, kb + 64);
    for (int i = 0; i < nch; ++i) {
        if (i + 1 < nch) waitg1(); else waitg0();
        __syncthreads();
        const u32 buf = sb + base + (u32)((i & 1) * 65536);
        mma_tile(acc, buf + F_AH, buf + F_AL, buf + F_WH, buf + F_WL);
        __syncthreads();
        if (i + 2 < nch)
            issue_full(sb + base + (u32)((i & 1) * 65536), Ah, Al, lda, Wh, Wl, ldw,
                       kb + 64 * (i + 2));
    }
}

// Dump 128x128 fp32 accumulator tile (tile-local coords, ldc fixed 128).
__device__ __forceinline__ void dump_loc(const float (&acc)[4][4][4],
                                         float *__restrict__ dst)
{
    const int lid = threadIdx.x & 31, wid = threadIdx.x >> 5;
    const int wm = wid >> 2, wn = wid & 3;
    const int g = lid >> 2, t = lid & 3;
#pragma unroll
    for (int ma = 0; ma < 4; ++ma)
#pragma unroll
        for (int na = 0; na < 4; ++na) {
            const int row = wm * 64 + ma * 16 + g;
            const int col = wn * 32 + na * 8 + t * 2;
            *reinterpret_cast<float2 *>(&dst[row * 128 + col]) =
                make_float2(acc[ma][na][0], acc[ma][na][1]);
            *reinterpret_cast<float2 *>(&dst[(row + 8) * 128 + col]) =
                make_float2(acc[ma][na][2], acc[ma][na][3]);
        }
}

// In-stage merge (validated R14): CTA merges rows [myks*16, +16) of its tile.
__device__ __forceinline__ void merge_h(
    const float *__restrict__ tbase, int myks, int cnt,
    const float *__restrict__ bias, int m0, int n0,
    __nv_bfloat16 *__restrict__ dh, __nv_bfloat16 *__restrict__ dl)
{
    const int t = threadIdx.x;
    const int row = myks * 16 + (t >> 4);
    const int c = (t & 15) * 8;
    const float *p = tbase + row * 128 + c;
    float4 a0 = __ldcg(reinterpret_cast<const float4 *>(p));
    float4 a1 = __ldcg(reinterpret_cast<const float4 *>(p + 4));
    for (int q = 1; q < cnt; ++q) {
        const float *pp = p + q * TILE_F;
        const float4 b0 = __ldcg(reinterpret_cast<const float4 *>(pp));
        const float4 b1 = __ldcg(reinterpret_cast<const float4 *>(pp + 4));
        a0.x += b0.x; a0.y += b0.y; a0.z += b0.z; a0.w += b0.w;
        a1.x += b1.x; a1.y += b1.y; a1.z += b1.z; a1.w += b1.w;
    }
    const float4 vb0 = *reinterpret_cast<const float4 *>(&bias[n0 + c]);
    const float4 vb1 = *reinterpret_cast<const float4 *>(&bias[n0 + c + 4]);
    const float o0 = tanhf(a0.x + vb0.x), o1 = tanhf(a0.y + vb0.y);
    const float o2 = tanhf(a0.z + vb0.z), o3 = tanhf(a0.w + vb0.w);
    const float o4 = tanhf(a1.x + vb1.x), o5 = tanhf(a1.y + vb1.y);
    const float o6 = tanhf(a1.z + vb1.z), o7 = tanhf(a1.w + vb1.w);
    __nv_bfloat16 h0, l0, h1, l1;
    const long base = (long)(m0 + row) * Hd + n0 + c;
    __nv_bfloat162 *oh = reinterpret_cast<__nv_bfloat162 *>(&dh[base]);
    __nv_bfloat162 *ol = reinterpret_cast<__nv_bfloat162 *>(&dl[base]);
    split_bf16(o0, h0, l0); split_bf16(o1, h1, l1);
    oh[0] = __halves2bfloat162(h0, h1); ol[0] = __halves2bfloat162(l0, l1);
    split_bf16(o2, h0, l0); split_bf16(o3, h1, l1);
    oh[1] = __halves2bfloat162(h0, h1); ol[1] = __halves2bfloat162(l0, l1);
    split_bf16(o4, h0, l0); split_bf16(o5, h1, l1);
    oh[2] = __halves2bfloat162(h0, h1); ol[2] = __halves2bfloat162(l0, l1);
    split_bf16(o6, h0, l0); split_bf16(o7, h1, l1);
    oh[3] = __halves2bfloat162(h0, h1); ol[3] = __halves2bfloat162(l0, l1);
}

__device__ __forceinline__ void convert_split(
    const float *__restrict__ s, __nv_bfloat16 *dh, __nv_bfloat16 *dl, int n, int gtid)
{
    for (int i = gtid; i < n; i += NCTA * NTHR) split_bf16(s[i], dh[i], dl[i]);
}

// Final-GEMM epilogue: out[:, s, :] tile = acc + fc_b.
__device__ __forceinline__ void final_store(
    const float (&acc)[4][4][4], float *__restrict__ out,
    const float *__restrict__ fc_b, int s, int m0, int n0)
{
    const int lid = threadIdx.x & 31, wid = threadIdx.x >> 5;
    const int wm = wid >> 2, wn = wid & 3;
    const int g = lid >> 2, t = lid & 3;
#pragma unroll
    for (int ma = 0; ma < 4; ++ma)
#pragma unroll
        for (int na = 0; na < 4; ++na) {
            const int row = m0 + wm * 64 + ma * 16 + g;
            const int col = n0 + wn * 32 + na * 8 + t * 2;
            const float bx = fc_b[col], by = fc_b[col + 1];
            *reinterpret_cast<float2 *>(
                &out[(long)row * (Tt * Ind) + (long)s * Ind + col]) =
                make_float2(acc[ma][na][0] + bx, acc[ma][na][1] + by);
            *reinterpret_cast<float2 *>(
                &out[(long)(row + 8) * (Tt * Ind) + (long)s * Ind + col]) =
                make_float2(acc[ma][na][2] + bx, acc[ma][na][3] + by);
        }
}

// M0 dump with global coords (phase 0b only; ldc = Hd).
__device__ __forceinline__ void dump_glob(
    const float (&acc)[4][4][4], float *__restrict__ dst, int m0, int n0)
{
    const int lid = threadIdx.x & 31, wid = threadIdx.x >> 5;
    const int wm = wid >> 2, wn = wid & 3;
    const int g = lid >> 2, t = lid & 3;
#pragma unroll
    for (int ma = 0; ma < 4; ++ma)
#pragma unroll
        for (int na = 0; na < 4; ++na) {
            const int row = m0 + wm * 64 + ma * 16 + g;
            const int col = n0 + wn * 32 + na * 8 + t * 2;
            *reinterpret_cast<float2 *>(&dst[(long)row * Hd + col]) =
                make_float2(acc[ma][na][0], acc[ma][na][1]);
            *reinterpret_cast<float2 *>(&dst[(long)(row + 8) * Hd + col]) =
                make_float2(acc[ma][na][2], acc[ma][na][3]);
        }
}

__global__ void __launch_bounds__(NTHR, 1) rnn_tc(
    const float *__restrict__ y0,
    const float *__restrict__ W_ih0, const float *__restrict__ W_hh0,
    const float *__restrict__ b_ih0, const float *__restrict__ b_hh0,
    const float *__restrict__ W_ih1, const float *__restrict__ W_hh1,
    const float *__restrict__ b_ih1, const float *__restrict__ b_hh1,
    const float *__restrict__ fc_W, const float *__restrict__ fc_b,
    float *__restrict__ out)
{
    extern __shared__ char smem[];
    const u32 sb = smem_u32(smem);
    const int tid = threadIdx.x, bid = blockIdx.x;
    const int gtid = bid * NTHR + tid;
    const int stride = NCTA * NTHR;

    // ---- phase 0a (every replay): splits, transpose, init, biases, counters
    convert_split(W_ih0, g_Wih0h, g_Wih0l, Hd * Ind, gtid);
    convert_split(W_hh0, g_Whh0h, g_Whh0l, Hd * Hd, gtid);
    convert_split(W_ih1, g_Wih1h, g_Wih1l, Hd * Hd, gtid);
    convert_split(W_hh1, g_Whh1h, g_Whh1l, Hd * Hd, gtid);
    convert_split(fc_W, g_fcWh, g_fcWl, Ind * Hd, gtid);
    for (int i = gtid; i < Hd * Ind; i += stride) {  // fcWT[j][k] = fc_W[k][j]
        const int j = i >> 8, k = i & 255;
        split_bf16(fc_W[(long)k * Hd + j], g_fcWTh[i], g_fcWTl[i]);
    }
    for (int i = gtid; i < Bm * Ind; i += stride) {
        const float v = y0[i];
        split_bf16(v, g_yh[i], g_yl[i]);
        out[(long)(i >> 8) * (Tt * Ind) + (i & 255)] = v;  // out[:, 0, :]
    }
    for (int i = gtid; i < BmHd; i += stride) {
        const __nv_bfloat16 z = __float2bfloat16(0.0f);
        g_h0h[0][i] = z; g_h0l[0][i] = z;
        g_H1h[i] = z;    g_H1l[i] = z;   // history slot 0 = h1 initial state
    }
    for (int j = gtid; j < Hd; j += stride) {
        const float s1 = b_ih0[j] + b_hh0[j];
        g_biasA1[j] = s1;
        float a = 0.0f;
        const float *wr = &W_ih0[(long)j * Ind];
        for (int k = 0; k < Ind; ++k) a += wr[k] * fc_b[k];
        g_biasAf[j] = a + s1;              // fc_b @ W_ih0^T + b_ih0 + b_hh0
        g_biasB[j] = b_ih1[j] + b_hh1[j];
    }
    if (gtid < 16) g_tcnt[gtid] = 0;
    grid_sync();

    // ---- phase 0b: M0 = W_ih0 @ fc_W  (1024x1024, K=256), 64 tiles x 2 k-splits
    {
        const int kk = bid >> 6, tj = bid & 63, tm = tj >> 3, tn = tj & 7;
        float acc[4][4][4] = {};
        gemm_full(acc, sb, 0,
                  g_Wih0h + (long)tm * 128 * Ind, g_Wih0l + (long)tm * 128 * Ind, Ind,
                  g_fcWTh + (long)tn * 128 * Ind, g_fcWTl + (long)tn * 128 * Ind, Ind,
                  kk * 128, 2);
        dump_glob(acc, &g_part[0] + (long)kk * Hd * Hd, tm * 128, tn * 128);
    }
    grid_sync();
    {   // M0 reduce + split to bf16 hi/lo
        const float *p0 = &g_part[0];
        const float *p1 = p0 + (long)Hd * Hd;
        for (int i = gtid * 4; i < Hd * Hd; i += stride * 4) {
            const float4 a = __ldcg(reinterpret_cast<const float4 *>(&p0[i]));
            const float4 b = __ldcg(reinterpret_cast<const float4 *>(&p1[i]));
            split_bf16(a.x + b.x, g_M0h[i], g_M0l[i]);
            split_bf16(a.y + b.y, g_M0h[i + 1], g_M0l[i + 1]);
            split_bf16(a.z + b.z, g_M0h[i + 2], g_M0l[i + 2]);
            split_bf16(a.w + b.w, g_M0h[i + 3], g_M0l[i + 3]);
        }
    }
    grid_sync();

    // tile mapping (R8/R14): 8 k-splits x (2m x 8n) over [256, 1024]
    const int ksAB = bid >> 4;
    const int tile = bid & 15;
    const int m0AB = ((bid >> 3) & 1) * 128, n0AB = (bid & 7) * 128;
    float *tbase = g_part + (long)tile * 8 * TILE_F;
    float *mypart = tbase + ksAB * TILE_F;
    u32 expv = 0;

    // ---- load resident W-hi slices (after M0 is final)
    {
        const __nv_bfloat16 *wa = (ksAB < 4)
            ? g_M0h + (long)n0AB * Hd + ksAB * 256
            : g_Whh0h + (long)n0AB * Hd + (ksAB - 4) * 256;
        const __nv_bfloat16 *wb = (ksAB < 4)
            ? g_Wih1h + (long)n0AB * Hd + ksAB * 256
            : g_Whh1h + (long)n0AB * Hd + (ksAB - 4) * 256;
#pragma unroll
        for (int c = 0; c < 4; ++c) {
            stage_async(sb + RW_A + (u32)c * 16384u, wa, Hd, c * 64);
            stage_async(sb + RW_B + (u32)c * 16384u, wb, Hd, c * 64);
        }
        commitg(); waitg0();
        __syncthreads();
    }

    for (int s = 1; s < Tt; ++s) {
        const int cb = (s - 1) & 1, nb = s & 1;
        const __nv_bfloat16 *h1ph = g_H1h + (long)(s - 1) * BmHd;
        const __nv_bfloat16 *h1pl = g_H1l + (long)(s - 1) * BmHd;

        // ---- stage A: h0(s) = tanh(h1(s-1)@M0^T + h0(s-1)@Whh0^T + biasAf)
        {
            const int nprod = (s == 1) ? 4 : 8;
            const bool iproduce = (s == 1) ? (ksAB < 4) : true;
            if (iproduce) {
                float acc[4][4][4] = {};
                if (s == 1) {
                    // single chunk: y0 @ Wih0 (kb = ksAB*64); Wh parked in BUF1
                    const int kb = ksAB * 64;
                    stage_async(sb + BUF0 + B_AH, g_yh + (long)m0AB * Ind, Ind, kb);
                    stage_async(sb + BUF0 + B_AL, g_yl + (long)m0AB * Ind, Ind, kb);
                    stage_async(sb + BUF0 + B_WL, g_Wih0l + (long)n0AB * Ind, Ind, kb);
                    stage_async(sb + BUF1 + B_AH, g_Wih0h + (long)n0AB * Ind, Ind, kb);
                    commitg(); waitg0();
                    __syncthreads();
                    mma_tile(acc, sb + BUF0 + B_AH, sb + BUF0 + B_AL,
                             sb + BUF1 + B_AH, sb + BUF0 + B_WL);
                    __syncthreads();
                } else if (ksAB < 4) {
                    gemm_res(acc, sb,
                             h1ph + (long)m0AB * Hd, h1pl + (long)m0AB * Hd, Hd,
                             g_M0l + (long)n0AB * Hd, Hd, RW_A, ksAB * 256, 4);
                } else {
                    gemm_res(acc, sb,
                             g_h0h[cb] + (long)m0AB * Hd, g_h0l[cb] + (long)m0AB * Hd, Hd,
                             g_Whh0l + (long)n0AB * Hd, Hd, RW_A, (ksAB - 4) * 256, 4);
                }
                dump_loc(acc, mypart);
            }
            expv += (u32)nprod;
            tile_sync(tile, iproduce, expv);
            merge_h(tbase, ksAB, nprod, s == 1 ? g_biasA1 : g_biasAf,
                    m0AB, n0AB, g_h0h[nb], g_h0l[nb]);
        }
        grid_sync();

        // ---- stage B: h1(s) = tanh(h0(s)@Wih1^T + h1(s-1)@Whh1^T + biasB)
        {
            float acc[4][4][4] = {};
            if (ksAB < 4)
                gemm_res(acc, sb,
                         g_h0h[nb] + (long)m0AB * Hd, g_h0l[nb] + (long)m0AB * Hd, Hd,
                         g_Wih1l + (long)n0AB * Hd, Hd, RW_B, ksAB * 256, 4);
            else
                gemm_res(acc, sb,
                         h1ph + (long)m0AB * Hd, h1pl + (long)m0AB * Hd, Hd,
                         g_Whh1l + (long)n0AB * Hd, Hd, RW_B, (ksAB - 4) * 256, 4);
            dump_loc(acc, mypart);
            expv += 8u;
            tile_sync(tile, true, expv);
            merge_h(tbase, ksAB, 8, g_biasB, m0AB, n0AB,
                    g_H1h + (long)s * BmHd, g_H1l + (long)s * BmHd);
        }
        grid_sync();
    }

    // ---- batched output GEMM: out[:, s, :] = H1[s] @ fc_W^T + fc_b, s = 1..511
    // (residents dead; full-staging buffers reuse smem [0,128K))
    for (int job = bid; job < (Tt - 1) * 4; job += NCTA) {
        const int ntile = job & 1;
        const int rt = job >> 1;
        const int s = 1 + (rt >> 1);
        const int m0 = (rt & 1) * 128, n0 = ntile * 128;
        float acc[4][4][4] = {};
        gemm_full(acc, sb, 0,
                  g_H1h + (long)s * BmHd + (long)m0 * Hd,
                  g_H1l + (long)s * BmHd + (long)m0 * Hd, Hd,
                  g_fcWh + (long)n0 * Hd, g_fcWl + (long)n0 * Hd, Hd,
                  0, 16);
        final_store(acc, out, fc_b, s, m0, n0);
    }
}

extern "C" void kernel_launch(void *const *d_in, const int *in_sizes, int n_in,
                              void *d_out, int out_size) {
    (void)in_sizes; (void)n_in; (void)out_size;
    const float *y0    = (const float *)d_in[0];
    // d_in[1] = t (length only; unused)
    const float *W_ih0 = (const float *)d_in[2];
    const float *W_hh0 = (const float *)d_in[3];
    const float *b_ih0 = (const float *)d_in[4];
    const float *b_hh0 = (const float *)d_in[5];
    const float *W_ih1 = (const float *)d_in[6];
    const float *W_hh1 = (const float *)d_in[7];
    const float *b_ih1 = (const float *)d_in[8];
    const float *b_hh1 = (const float *)d_in[9];
    const float *fc_W  = (const float *)d_in[10];
    const float *fc_b  = (const float *)d_in[11];
    float *out = (float *)d_out;

    cudaFuncSetAttribute(rnn_tc, cudaFuncAttributeMaxDynamicSharedMemorySize, SMEM_BYTES);
    rnn_tc<<<NCTA, NTHR, SMEM_BYTES>>>(y0, W_ih0, W_hh0, b_ih0, b_hh0,
                                       W_ih1, W_hh1, b_ih1, b_hh1,
                                       fc_W, fc_b, out);
}

// round 16
// speedup vs baseline: 1.2060x; 1.2060x over previous
#include <cuda_runtime.h>
#include <cuda_fp16.h>

// Persistent 2-layer tanh RNN, sm_103 tensor cores (mma.sync FP16, 2-pass).
// R16 = R14 skeleton (15.24ms best: 128 CTAs, 128x128 tiles, 8-way split-K,
// in-stage merge, 2 barriers/step, fc folded via M0, batched output GEMM)
// with the precision scheme changed: fp16 split WEIGHTS (Wh+Wl, ~22-bit) x
// single-fp16 ACTIVATIONS -> 2 MMA passes per atom instead of 3.
// Rationale: tensor% pinned at 36-38% across R9-R15 while every non-GEMM
// hypothesis (latency, barriers, staging count, L2 bytes, warps) tested null
// => legacy mma.sync path is MAC-ceiling-bound; only fewer MACs can win.

typedef unsigned long long u64;
typedef unsigned int u32;

namespace {
constexpr int NCTA = 128;
constexpr int NTHR = 256;
constexpr int Bm = 256, Hd = 1024, Ind = 256, Tt = 512;
constexpr int BmHd = Bm * Hd;
constexpr int TILE_F = 128 * 128;
// double-buffered smem: per buffer 3 fp16 tiles {A, Wh, Wl} x 16KB
constexpr u32 T_A = 0, T_WH = 16384, T_WL = 32768;
constexpr u32 BUFB = 49152;
constexpr int SMEM_BYTES = 2 * BUFB;  // 96KB
}

// ---- device-global state (allocation-free rule) ----
__device__ __align__(16) __half g_Wih0h[Hd * Ind], g_Wih0l[Hd * Ind];
__device__ __align__(16) __half g_Whh0h[Hd * Hd],  g_Whh0l[Hd * Hd];
__device__ __align__(16) __half g_Wih1h[Hd * Hd],  g_Wih1l[Hd * Hd];
__device__ __align__(16) __half g_Whh1h[Hd * Hd],  g_Whh1l[Hd * Hd];
__device__ __align__(16) __half g_M0h[Hd * Hd],    g_M0l[Hd * Hd];
__device__ __align__(16) __half g_fcWh[Ind * Hd],  g_fcWl[Ind * Hd];
__device__ __align__(16) __half g_fcWTh[Hd * Ind], g_fcWTl[Hd * Ind];
__device__ __align__(16) __half g_y[Bm * Ind];
__device__ __align__(16) __half g_h0[2][BmHd];
__device__ __align__(16) __half g_H1[Tt * BmHd];  // h1 history (single fp16)
__device__ float g_biasA1[Hd], g_biasAf[Hd], g_biasB[Hd];
__device__ float g_part[16 * 8 * TILE_F];
__device__ u32 g_tcnt[16];
__device__ unsigned g_arrive = 0, g_gen = 0;

// ---- helpers ----
__device__ __forceinline__ u32 smem_u32(const void *p) {
    u32 a;
    asm("{ .reg .u64 t; cvta.to.shared.u64 t, %1; cvt.u32.u64 %0, t; }"
        : "=r"(a) : "l"(p));
    return a;
}

#define LDMX4(r, a) \
    asm volatile("ldmatrix.sync.aligned.m8n8.x4.shared.b16 {%0,%1,%2,%3}, [%4];" \
                 : "=r"((r)[0]), "=r"((r)[1]), "=r"((r)[2]), "=r"((r)[3]) : "r"(a))

__device__ __forceinline__ void mma16816(float *c, const u32 *a, u32 b0, u32 b1) {
    asm volatile(
        "mma.sync.aligned.m16n8k16.row.col.f32.f16.f16.f32 "
        "{%0,%1,%2,%3}, {%4,%5,%6,%7}, {%8,%9}, {%0,%1,%2,%3};"
        : "+f"(c[0]), "+f"(c[1]), "+f"(c[2]), "+f"(c[3])
        : "r"(a[0]), "r"(a[1]), "r"(a[2]), "r"(a[3]), "r"(b0), "r"(b1));
}

__device__ __forceinline__ void commitg() {
    asm volatile("cp.async.commit_group;" ::: "memory");
}
__device__ __forceinline__ void waitg0() {
    asm volatile("cp.async.wait_group 0;" ::: "memory");
}
__device__ __forceinline__ void waitg1() {
    asm volatile("cp.async.wait_group 1;" ::: "memory");
}

// ---- grid barrier (validated R4-R15) ----
__device__ __forceinline__ void grid_sync() {
    __syncthreads();
    if (threadIdx.x == 0) {
        unsigned gen = *(volatile unsigned *)&g_gen;
        __threadfence();
        if (atomicAdd(&g_arrive, 1u) == NCTA - 1) {
            atomicExch(&g_arrive, 0u);
            __threadfence();
            atomicAdd(&g_gen, 1u);
        } else {
            while (*(volatile unsigned *)&g_gen == gen) { }
            __threadfence();
        }
    }
    __syncthreads();
}

// per-tile sub-barrier (validated R14/R15)
__device__ __forceinline__ void tile_sync(int tile, bool produce, u32 target) {
    __syncthreads();
    if (threadIdx.x == 0) {
        if (produce) {
            __threadfence();
            atomicAdd(&g_tcnt[tile], 1u);
        }
        while (*(volatile u32 *)&g_tcnt[tile] < target) { }
        __threadfence();
    }
    __syncthreads();
}

__device__ __forceinline__ void split_fp16(float v, __half &h, __half &l) {
    h = __float2half(v);
    l = __float2half(v - __half2float(h));
}

// cp.async one 128x64 fp16 tile (SW128 xor swizzle) into smem.
__device__ __forceinline__ void stage_async(u32 sdst, const __half *g,
                                            int ld, int kb) {
    const int tid = threadIdx.x;
#pragma unroll
    for (int j = 0; j < 4; ++j) {
        const int u = tid + NTHR * j;
        const int row = u >> 3, blk = u & 7;
        const size_t src = __cvta_generic_to_global(&g[(long)row * ld + kb + blk * 8]);
        const u32 dst = sdst + row * 128 + ((blk ^ (row & 7)) << 4);
        asm volatile("cp.async.cg.shared.global [%0], [%1], 16;"
                     :: "r"(dst), "l"(src) : "memory");
    }
}

// chunk = {A, Wh, Wl}
__device__ __forceinline__ void issue_chunk(
    u32 buf, const __half *A, int lda,
    const __half *Wh, const __half *Wl, int ldw, int kb) {
    stage_async(buf + T_A, A, lda, kb);
    stage_async(buf + T_WH, Wh, ldw, kb);
    stage_async(buf + T_WL, Wl, ldw, kb);
    commitg();
}

// MMA over one staged 64-k chunk. 8 warps as 2x4; warp tile 64x32
// (4 m-atoms x 4 n-atoms). 2 passes: a*wh + a*wl (fp32 acc).
__device__ __forceinline__ void mma_tile(float (&acc)[4][4][4], u32 sbase) {
    const int lid = threadIdx.x & 31, wid = threadIdx.x >> 5;
    const int wm = wid >> 2, wn = wid & 3;
    const int rA0 = wm * 64 + (lid & 7) + ((lid >> 3) & 1) * 8;
    const int cAsel = (lid >> 4) & 1;
    const int rB0 = wn * 32 + (lid & 7) + ((lid >> 4) & 1) * 8;
    const int cBsel = (lid >> 3) & 1;
#pragma unroll
    for (int k16 = 0; k16 < 4; ++k16) {
        u32 a[4][4], bh[2][4], bl[2][4];
#pragma unroll
        for (int ma = 0; ma < 4; ++ma) {
            const int r = rA0 + ma * 16;
            const u32 off = (u32)(r * 128 + (((k16 * 2 + cAsel) ^ (r & 7)) << 4));
            LDMX4(a[ma], sbase + T_A + off);
        }
#pragma unroll
        for (int p = 0; p < 2; ++p) {
            const int r = rB0 + p * 16;
            const u32 off = (u32)(r * 128 + (((k16 * 2 + cBsel) ^ (r & 7)) << 4));
            LDMX4(bh[p], sbase + T_WH + off);
            LDMX4(bl[p], sbase + T_WL + off);
        }
#pragma unroll
        for (int ma = 0; ma < 4; ++ma)
#pragma unroll
            for (int na = 0; na < 4; ++na) {
                const int p = na >> 1, q = (na & 1) * 2;
                mma16816(acc[ma][na], a[ma], bh[p][q], bh[p][q + 1]);
                mma16816(acc[ma][na], a[ma], bl[p][q], bl[p][q + 1]);
            }
    }
}

// Double-buffered pipelined GEMM over nch 64-k chunks starting at kb.
__device__ __forceinline__ void gemm_pipe(
    float (&acc)[4][4][4], u32 sb,
    const __half *A, int lda,
    const __half *Wh, const __half *Wl, int ldw,
    int kb, int nch)
{
    issue_chunk(sb, A, lda, Wh, Wl, ldw, kb);
    if (nch > 1) issue_chunk(sb + BUFB, A, lda, Wh, Wl, ldw, kb + 64);
    for (int i = 0; i < nch; ++i) {
        if (i + 1 < nch) waitg1(); else waitg0();
        __syncthreads();
        mma_tile(acc, sb + (u32)((i & 1) * BUFB));
        __syncthreads();
        if (i + 2 < nch)
            issue_chunk(sb + (u32)((i & 1) * BUFB), A, lda, Wh, Wl, ldw,
                        kb + 64 * (i + 2));
    }
}

// Dump 128x128 fp32 accumulator tile (tile-local coords, ldc fixed 128).
__device__ __forceinline__ void dump_loc(const float (&acc)[4][4][4],
                                         float *__restrict__ dst)
{
    const int lid = threadIdx.x & 31, wid = threadIdx.x >> 5;
    const int wm = wid >> 2, wn = wid & 3;
    const int g = lid >> 2, t = lid & 3;
#pragma unroll
    for (int ma = 0; ma < 4; ++ma)
#pragma unroll
        for (int na = 0; na < 4; ++na) {
            const int row = wm * 64 + ma * 16 + g;
            const int col = wn * 32 + na * 8 + t * 2;
            *reinterpret_cast<float2 *>(&dst[row * 128 + col]) =
                make_float2(acc[ma][na][0], acc[ma][na][1]);
            *reinterpret_cast<float2 *>(&dst[(row + 8) * 128 + col]) =
                make_float2(acc[ma][na][2], acc[ma][na][3]);
        }
}

// In-stage merge (validated R14): CTA merges rows [myks*16, +16) of its tile:
// sum cnt partials + bias, tanh, write SINGLE fp16 activations.
__device__ __forceinline__ void merge_h(
    const float *__restrict__ tbase, int myks, int cnt,
    const float *__restrict__ bias, int m0, int n0,
    __half *__restrict__ dh)
{
    const int t = threadIdx.x;
    const int row = myks * 16 + (t >> 4);
    const int c = (t & 15) * 8;
    const float *p = tbase + row * 128 + c;
    float4 a0 = __ldcg(reinterpret_cast<const float4 *>(p));
    float4 a1 = __ldcg(reinterpret_cast<const float4 *>(p + 4));
    for (int q = 1; q < cnt; ++q) {
        const float *pp = p + q * TILE_F;
        const float4 b0 = __ldcg(reinterpret_cast<const float4 *>(pp));
        const float4 b1 = __ldcg(reinterpret_cast<const float4 *>(pp + 4));
        a0.x += b0.x; a0.y += b0.y; a0.z += b0.z; a0.w += b0.w;
        a1.x += b1.x; a1.y += b1.y; a1.z += b1.z; a1.w += b1.w;
    }
    const float4 vb0 = *reinterpret_cast<const float4 *>(&bias[n0 + c]);
    const float4 vb1 = *reinterpret_cast<const float4 *>(&bias[n0 + c + 4]);
    __half2 h2[4];
    h2[0] = __floats2half2_rn(tanhf(a0.x + vb0.x), tanhf(a0.y + vb0.y));
    h2[1] = __floats2half2_rn(tanhf(a0.z + vb0.z), tanhf(a0.w + vb0.w));
    h2[2] = __floats2half2_rn(tanhf(a1.x + vb1.x), tanhf(a1.y + vb1.y));
    h2[3] = __floats2half2_rn(tanhf(a1.z + vb1.z), tanhf(a1.w + vb1.w));
    const long base = (long)(m0 + row) * Hd + n0 + c;
    *reinterpret_cast<uint4 *>(&dh[base]) = *reinterpret_cast<uint4 *>(h2);
}

__device__ __forceinline__ void convert_splitw(
    const float *__restrict__ s, __half *dh, __half *dl, int n, int gtid)
{
    for (int i = gtid; i < n; i += NCTA * NTHR) split_fp16(s[i], dh[i], dl[i]);
}

// Final-GEMM epilogue: out[:, s, :] tile = acc + fc_b.
__device__ __forceinline__ void final_store(
    const float (&acc)[4][4][4], float *__restrict__ out,
    const float *__restrict__ fc_b, int s, int m0, int n0)
{
    const int lid = threadIdx.x & 31, wid = threadIdx.x >> 5;
    const int wm = wid >> 2, wn = wid & 3;
    const int g = lid >> 2, t = lid & 3;
#pragma unroll
    for (int ma = 0; ma < 4; ++ma)
#pragma unroll
        for (int na = 0; na < 4; ++na) {
            const int row = m0 + wm * 64 + ma * 16 + g;
            const int col = n0 + wn * 32 + na * 8 + t * 2;
            const float bx = fc_b[col], by = fc_b[col + 1];
            *reinterpret_cast<float2 *>(
                &out[(long)row * (Tt * Ind) + (long)s * Ind + col]) =
                make_float2(acc[ma][na][0] + bx, acc[ma][na][1] + by);
            *reinterpret_cast<float2 *>(
                &out[(long)(row + 8) * (Tt * Ind) + (long)s * Ind + col]) =
                make_float2(acc[ma][na][2] + bx, acc[ma][na][3] + by);
        }
}

// M0 dump with global coords (phase 0b only; ldc = Hd).
__device__ __forceinline__ void dump_glob(
    const float (&acc)[4][4][4], float *__restrict__ dst, int m0, int n0)
{
    const int lid = threadIdx.x & 31, wid = threadIdx.x >> 5;
    const int wm = wid >> 2, wn = wid & 3;
    const int g = lid >> 2, t = lid & 3;
#pragma unroll
    for (int ma = 0; ma < 4; ++ma)
#pragma unroll
        for (int na = 0; na < 4; ++na) {
            const int row = m0 + wm * 64 + ma * 16 + g;
            const int col = n0 + wn * 32 + na * 8 + t * 2;
            *reinterpret_cast<float2 *>(&dst[(long)row * Hd + col]) =
                make_float2(acc[ma][na][0], acc[ma][na][1]);
            *reinterpret_cast<float2 *>(&dst[(long)(row + 8) * Hd + col]) =
                make_float2(acc[ma][na][2], acc[ma][na][3]);
        }
}

__global__ void __launch_bounds__(NTHR, 1) rnn_tc(
    const float *__restrict__ y0,
    const float *__restrict__ W_ih0, const float *__restrict__ W_hh0,
    const float *__restrict__ b_ih0, const float *__restrict__ b_hh0,
    const float *__restrict__ W_ih1, const float *__restrict__ W_hh1,
    const float *__restrict__ b_ih1, const float *__restrict__ b_hh1,
    const float *__restrict__ fc_W, const float *__restrict__ fc_b,
    float *__restrict__ out)
{
    extern __shared__ char smem[];
    const u32 sb = smem_u32(smem);
    const int tid = threadIdx.x, bid = blockIdx.x;
    const int gtid = bid * NTHR + tid;
    const int stride = NCTA * NTHR;

    // ---- phase 0a (every replay): weight splits, transpose, init, biases
    convert_splitw(W_ih0, g_Wih0h, g_Wih0l, Hd * Ind, gtid);
    convert_splitw(W_hh0, g_Whh0h, g_Whh0l, Hd * Hd, gtid);
    convert_splitw(W_ih1, g_Wih1h, g_Wih1l, Hd * Hd, gtid);
    convert_splitw(W_hh1, g_Whh1h, g_Whh1l, Hd * Hd, gtid);
    convert_splitw(fc_W, g_fcWh, g_fcWl, Ind * Hd, gtid);
    for (int i = gtid; i < Hd * Ind; i += stride) {  // fcWT[j][k] = fc_W[k][j]
        const int j = i >> 8, k = i & 255;
        split_fp16(fc_W[(long)k * Hd + j], g_fcWTh[i], g_fcWTl[i]);
    }
    for (int i = gtid; i < Bm * Ind; i += stride) {
        const float v = y0[i];
        g_y[i] = __float2half(v);
        out[(long)(i >> 8) * (Tt * Ind) + (i & 255)] = v;  // out[:, 0, :]
    }
    for (int i = gtid; i < BmHd; i += stride) {
        const __half z = __float2half(0.0f);
        g_h0[0][i] = z;
        g_H1[i] = z;                       // history slot 0 = h1 initial state
    }
    for (int j = gtid; j < Hd; j += stride) {
        const float s1 = b_ih0[j] + b_hh0[j];
        g_biasA1[j] = s1;
        float a = 0.0f;
        const float *wr = &W_ih0[(long)j * Ind];
        for (int k = 0; k < Ind; ++k) a += wr[k] * fc_b[k];
        g_biasAf[j] = a + s1;              // fc_b @ W_ih0^T + b_ih0 + b_hh0
        g_biasB[j] = b_ih1[j] + b_hh1[j];
    }
    if (gtid < 16) g_tcnt[gtid] = 0;
    grid_sync();

    // ---- phase 0b: M0 = W_ih0 @ fc_W (1024x1024, K=256), 64 tiles x 2 k-splits
    // A operand = Wih0 hi limb (single fp16), W operand = fcWT split.
    {
        const int kk = bid >> 6, tj = bid & 63, tm = tj >> 3, tn = tj & 7;
        float acc[4][4][4] = {};
        gemm_pipe(acc, sb,
                  g_Wih0h + (long)tm * 128 * Ind, Ind,
                  g_fcWTh + (long)tn * 128 * Ind, g_fcWTl + (long)tn * 128 * Ind, Ind,
                  kk * 128, 2);
        dump_glob(acc, &g_part[0] + (long)kk * Hd * Hd, tm * 128, tn * 128);
    }
    grid_sync();
    {   // M0 reduce + split to fp16 hi/lo
        const float *p0 = &g_part[0];
        const float *p1 = p0 + (long)Hd * Hd;
        for (int i = gtid * 4; i < Hd * Hd; i += stride * 4) {
            const float4 a = __ldcg(reinterpret_cast<const float4 *>(&p0[i]));
            const float4 b = __ldcg(reinterpret_cast<const float4 *>(&p1[i]));
            split_fp16(a.x + b.x, g_M0h[i], g_M0l[i]);
            split_fp16(a.y + b.y, g_M0h[i + 1], g_M0l[i + 1]);
            split_fp16(a.z + b.z, g_M0h[i + 2], g_M0l[i + 2]);
            split_fp16(a.w + b.w, g_M0h[i + 3], g_M0l[i + 3]);
        }
    }
    grid_sync();

    // tile mapping (R8/R14): 8 k-splits x (2m x 8n) over [256, 1024]
    const int ksAB = bid >> 4;
    const int tile = bid & 15;
    const int m0AB = ((bid >> 3) & 1) * 128, n0AB = (bid & 7) * 128;
    float *tbase = g_part + (long)tile * 8 * TILE_F;
    float *mypart = tbase + ksAB * TILE_F;
    u32 expv = 0;

    for (int s = 1; s < Tt; ++s) {
        const int cb = (s - 1) & 1, nb = s & 1;
        const __half *h1p = g_H1 + (long)(s - 1) * BmHd;

        // ---- stage A: h0(s) = tanh(h1(s-1)@M0^T + h0(s-1)@Whh0^T + biasAf)
        {
            const int nprod = (s == 1) ? 4 : 8;
            const bool iproduce = (s == 1) ? (ksAB < 4) : true;
            if (iproduce) {
                float acc[4][4][4] = {};
                if (ksAB < 4) {
                    if (s == 1)
                        gemm_pipe(acc, sb,
                                  g_y + (long)m0AB * Ind, Ind,
                                  g_Wih0h + (long)n0AB * Ind,
                                  g_Wih0l + (long)n0AB * Ind, Ind,
                                  ksAB * 64, 1);
                    else
                        gemm_pipe(acc, sb,
                                  h1p + (long)m0AB * Hd, Hd,
                                  g_M0h + (long)n0AB * Hd,
                                  g_M0l + (long)n0AB * Hd, Hd,
                                  ksAB * 256, 4);
                } else {
                    gemm_pipe(acc, sb,
                              g_h0[cb] + (long)m0AB * Hd, Hd,
                              g_Whh0h + (long)n0AB * Hd,
                              g_Whh0l + (long)n0AB * Hd, Hd,
                              (ksAB - 4) * 256, 4);
                }
                dump_loc(acc, mypart);
            }
            expv += (u32)nprod;
            tile_sync(tile, iproduce, expv);
            merge_h(tbase, ksAB, nprod, s == 1 ? g_biasA1 : g_biasAf,
                    m0AB, n0AB, g_h0[nb]);
        }
        grid_sync();

        // ---- stage B: h1(s) = tanh(h0(s)@Wih1^T + h1(s-1)@Whh1^T + biasB)
        {
            float acc[4][4][4] = {};
            if (ksAB < 4)
                gemm_pipe(acc, sb,
                          g_h0[nb] + (long)m0AB * Hd, Hd,
                          g_Wih1h + (long)n0AB * Hd,
                          g_Wih1l + (long)n0AB * Hd, Hd,
                          ksAB * 256, 4);
            else
                gemm_pipe(acc, sb,
                          h1p + (long)m0AB * Hd, Hd,
                          g_Whh1h + (long)n0AB * Hd,
                          g_Whh1l + (long)n0AB * Hd, Hd,
                          (ksAB - 4) * 256, 4);
            dump_loc(acc, mypart);
            expv += 8u;
            tile_sync(tile, true, expv);
            merge_h(tbase, ksAB, 8, g_biasB, m0AB, n0AB,
                    g_H1 + (long)s * BmHd);
        }
        grid_sync();
    }

    // ---- batched output GEMM: out[:, s, :] = H1[s] @ fc_W^T + fc_b, s = 1..511
    for (int job = bid; job < (Tt - 1) * 4; job += NCTA) {
        const int ntile = job & 1;
        const int rt = job >> 1;
        const int s = 1 + (rt >> 1);
        const int m0 = (rt & 1) * 128, n0 = ntile * 128;
        float acc[4][4][4] = {};
        gemm_pipe(acc, sb,
                  g_H1 + (long)s * BmHd + (long)m0 * Hd, Hd,
                  g_fcWh + (long)n0 * Hd, g_fcWl + (long)n0 * Hd, Hd,
                  0, 16);
        final_store(acc, out, fc_b, s, m0, n0);
    }
}

extern "C" void kernel_launch(void *const *d_in, const int *in_sizes, int n_in,
                              void *d_out, int out_size) {
    (void)in_sizes; (void)n_in; (void)out_size;
    const float *y0    = (const float *)d_in[0];
    // d_in[1] = t (length only; unused)
    const float *W_ih0 = (const float *)d_in[2];
    const float *W_hh0 = (const float *)d_in[3];
    const float *b_ih0 = (const float *)d_in[4];
    const float *b_hh0 = (const float *)d_in[5];
    const float *W_ih1 = (const float *)d_in[6];
    const float *W_hh1 = (const float *)d_in[7];
    const float *b_ih1 = (const float *)d_in[8];
    const float *b_hh1 = (const float *)d_in[9];
    const float *fc_W  = (const float *)d_in[10];
    const float *fc_b  = (const float *)d_in[11];
    float *out = (float *)d_out;

    cudaFuncSetAttribute(rnn_tc, cudaFuncAttributeMaxDynamicSharedMemorySize, SMEM_BYTES);
    rnn_tc<<<NCTA, NTHR, SMEM_BYTES>>>(y0, W_ih0, W_hh0, b_ih0, b_hh0,
                                       W_ih1, W_hh1, b_ih1, b_hh1,
                                       fc_W, fc_b, out);
}

// round 17
// speedup vs baseline: 1.4941x; 1.2390x over previous
#include <cuda_runtime.h>
#include <cuda_fp16.h>

// Persistent 2-layer tanh RNN, sm_103 tensor cores (mma.sync FP16, 1-PASS).
// R17 = R16 skeleton (12.76ms: 128 CTAs, 128x128 tiles, 8-way split-K,
// in-stage merge, 2 barriers/step, fc folded via M0, batched output GEMM)
// with single fp16 weights (no lo-limb): HMMA count halves again.
// Risk model calibrated on R16: activation-fp16 injection 1.2e-4/step gave
// final 1.32e-4 (amplification ~1.1). Weight-quant injection ~1.4e-4/GEMM
// coherent => predicted final 2.5-4e-4, 3x margin to the 1e-3 gate.

typedef unsigned long long u64;
typedef unsigned int u32;

namespace {
constexpr int NCTA = 128;
constexpr int NTHR = 256;
constexpr int Bm = 256, Hd = 1024, Ind = 256, Tt = 512;
constexpr int BmHd = Bm * Hd;
constexpr int TILE_F = 128 * 128;
// double-buffered smem: per buffer 2 fp16 tiles {A, W} x 16KB
constexpr u32 T_A = 0, T_W = 16384;
constexpr u32 BUFB = 32768;
constexpr int SMEM_BYTES = 2 * BUFB;  // 64KB
}

// ---- device-global state (allocation-free rule) ----
__device__ __align__(16) __half g_Wih0[Hd * Ind];
__device__ __align__(16) __half g_Whh0[Hd * Hd];
__device__ __align__(16) __half g_Wih1[Hd * Hd];
__device__ __align__(16) __half g_Whh1[Hd * Hd];
__device__ __align__(16) __half g_M0[Hd * Hd];
__device__ __align__(16) __half g_fcW[Ind * Hd];
__device__ __align__(16) __half g_fcWT[Hd * Ind];
__device__ __align__(16) __half g_y[Bm * Ind];
__device__ __align__(16) __half g_h0[2][BmHd];
__device__ __align__(16) __half g_H1[Tt * BmHd];  // h1 history (single fp16)
__device__ float g_biasA1[Hd], g_biasAf[Hd], g_biasB[Hd];
__device__ float g_part[16 * 8 * TILE_F];
__device__ u32 g_tcnt[16];
__device__ unsigned g_arrive = 0, g_gen = 0;

// ---- helpers ----
__device__ __forceinline__ u32 smem_u32(const void *p) {
    u32 a;
    asm("{ .reg .u64 t; cvta.to.shared.u64 t, %1; cvt.u32.u64 %0, t; }"
        : "=r"(a) : "l"(p));
    return a;
}

#define LDMX4(r, a) \
    asm volatile("ldmatrix.sync.aligned.m8n8.x4.shared.b16 {%0,%1,%2,%3}, [%4];" \
                 : "=r"((r)[0]), "=r"((r)[1]), "=r"((r)[2]), "=r"((r)[3]) : "r"(a))

__device__ __forceinline__ void mma16816(float *c, const u32 *a, u32 b0, u32 b1) {
    asm volatile(
        "mma.sync.aligned.m16n8k16.row.col.f32.f16.f16.f32 "
        "{%0,%1,%2,%3}, {%4,%5,%6,%7}, {%8,%9}, {%0,%1,%2,%3};"
        : "+f"(c[0]), "+f"(c[1]), "+f"(c[2]), "+f"(c[3])
        : "r"(a[0]), "r"(a[1]), "r"(a[2]), "r"(a[3]), "r"(b0), "r"(b1));
}

__device__ __forceinline__ void commitg() {
    asm volatile("cp.async.commit_group;" ::: "memory");
}
__device__ __forceinline__ void waitg0() {
    asm volatile("cp.async.wait_group 0;" ::: "memory");
}
__device__ __forceinline__ void waitg1() {
    asm volatile("cp.async.wait_group 1;" ::: "memory");
}

// ---- grid barrier (validated R4-R16) ----
__device__ __forceinline__ void grid_sync() {
    __syncthreads();
    if (threadIdx.x == 0) {
        unsigned gen = *(volatile unsigned *)&g_gen;
        __threadfence();
        if (atomicAdd(&g_arrive, 1u) == NCTA - 1) {
            atomicExch(&g_arrive, 0u);
            __threadfence();
            atomicAdd(&g_gen, 1u);
        } else {
            while (*(volatile unsigned *)&g_gen == gen) { }
            __threadfence();
        }
    }
    __syncthreads();
}

// per-tile sub-barrier (validated R14-R16)
__device__ __forceinline__ void tile_sync(int tile, bool produce, u32 target) {
    __syncthreads();
    if (threadIdx.x == 0) {
        if (produce) {
            __threadfence();
            atomicAdd(&g_tcnt[tile], 1u);
        }
        while (*(volatile u32 *)&g_tcnt[tile] < target) { }
        __threadfence();
    }
    __syncthreads();
}

// cp.async one 128x64 fp16 tile (SW128 xor swizzle) into smem.
__device__ __forceinline__ void stage_async(u32 sdst, const __half *g,
                                            int ld, int kb) {
    const int tid = threadIdx.x;
#pragma unroll
    for (int j = 0; j < 4; ++j) {
        const int u = tid + NTHR * j;
        const int row = u >> 3, blk = u & 7;
        const size_t src = __cvta_generic_to_global(&g[(long)row * ld + kb + blk * 8]);
        const u32 dst = sdst + row * 128 + ((blk ^ (row & 7)) << 4);
        asm volatile("cp.async.cg.shared.global [%0], [%1], 16;"
                     :: "r"(dst), "l"(src) : "memory");
    }
}

// chunk = {A, W}
__device__ __forceinline__ void issue_chunk(
    u32 buf, const __half *A, int lda, const __half *W, int ldw, int kb) {
    stage_async(buf + T_A, A, lda, kb);
    stage_async(buf + T_W, W, ldw, kb);
    commitg();
}

// MMA over one staged 64-k chunk. 8 warps as 2x4; warp tile 64x32
// (4 m-atoms x 4 n-atoms). SINGLE pass: a*w (fp32 acc).
__device__ __forceinline__ void mma_tile(float (&acc)[4][4][4], u32 sbase) {
    const int lid = threadIdx.x & 31, wid = threadIdx.x >> 5;
    const int wm = wid >> 2, wn = wid & 3;
    const int rA0 = wm * 64 + (lid & 7) + ((lid >> 3) & 1) * 8;
    const int cAsel = (lid >> 4) & 1;
    const int rB0 = wn * 32 + (lid & 7) + ((lid >> 4) & 1) * 8;
    const int cBsel = (lid >> 3) & 1;
#pragma unroll
    for (int k16 = 0; k16 < 4; ++k16) {
        u32 a[4][4], b[2][4];
#pragma unroll
        for (int ma = 0; ma < 4; ++ma) {
            const int r = rA0 + ma * 16;
            const u32 off = (u32)(r * 128 + (((k16 * 2 + cAsel) ^ (r & 7)) << 4));
            LDMX4(a[ma], sbase + T_A + off);
        }
#pragma unroll
        for (int p = 0; p < 2; ++p) {
            const int r = rB0 + p * 16;
            const u32 off = (u32)(r * 128 + (((k16 * 2 + cBsel) ^ (r & 7)) << 4));
            LDMX4(b[p], sbase + T_W + off);
        }
#pragma unroll
        for (int ma = 0; ma < 4; ++ma)
#pragma unroll
            for (int na = 0; na < 4; ++na) {
                const int p = na >> 1, q = (na & 1) * 2;
                mma16816(acc[ma][na], a[ma], b[p][q], b[p][q + 1]);
            }
    }
}

// Double-buffered pipelined GEMM over nch 64-k chunks starting at kb.
__device__ __forceinline__ void gemm_pipe(
    float (&acc)[4][4][4], u32 sb,
    const __half *A, int lda, const __half *W, int ldw,
    int kb, int nch)
{
    issue_chunk(sb, A, lda, W, ldw, kb);
    if (nch > 1) issue_chunk(sb + BUFB, A, lda, W, ldw, kb + 64);
    for (int i = 0; i < nch; ++i) {
        if (i + 1 < nch) waitg1(); else waitg0();
        __syncthreads();
        mma_tile(acc, sb + (u32)((i & 1) * BUFB));
        __syncthreads();
        if (i + 2 < nch)
            issue_chunk(sb + (u32)((i & 1) * BUFB), A, lda, W, ldw,
                        kb + 64 * (i + 2));
    }
}

// Dump 128x128 fp32 accumulator tile (tile-local coords, ldc fixed 128).
__device__ __forceinline__ void dump_loc(const float (&acc)[4][4][4],
                                         float *__restrict__ dst)
{
    const int lid = threadIdx.x & 31, wid = threadIdx.x >> 5;
    const int wm = wid >> 2, wn = wid & 3;
    const int g = lid >> 2, t = lid & 3;
#pragma unroll
    for (int ma = 0; ma < 4; ++ma)
#pragma unroll
        for (int na = 0; na < 4; ++na) {
            const int row = wm * 64 + ma * 16 + g;
            const int col = wn * 32 + na * 8 + t * 2;
            *reinterpret_cast<float2 *>(&dst[row * 128 + col]) =
                make_float2(acc[ma][na][0], acc[ma][na][1]);
            *reinterpret_cast<float2 *>(&dst[(row + 8) * 128 + col]) =
                make_float2(acc[ma][na][2], acc[ma][na][3]);
        }
}

// In-stage merge (validated R14-R16): CTA merges rows [myks*16, +16):
// sum cnt partials + bias, tanh, write single-fp16 activations.
__device__ __forceinline__ void merge_h(
    const float *__restrict__ tbase, int myks, int cnt,
    const float *__restrict__ bias, int m0, int n0,
    __half *__restrict__ dh)
{
    const int t = threadIdx.x;
    const int row = myks * 16 + (t >> 4);
    const int c = (t & 15) * 8;
    const float *p = tbase + row * 128 + c;
    float4 a0 = __ldcg(reinterpret_cast<const float4 *>(p));
    float4 a1 = __ldcg(reinterpret_cast<const float4 *>(p + 4));
    for (int q = 1; q < cnt; ++q) {
        const float *pp = p + q * TILE_F;
        const float4 b0 = __ldcg(reinterpret_cast<const float4 *>(pp));
        const float4 b1 = __ldcg(reinterpret_cast<const float4 *>(pp + 4));
        a0.x += b0.x; a0.y += b0.y; a0.z += b0.z; a0.w += b0.w;
        a1.x += b1.x; a1.y += b1.y; a1.z += b1.z; a1.w += b1.w;
    }
    const float4 vb0 = *reinterpret_cast<const float4 *>(&bias[n0 + c]);
    const float4 vb1 = *reinterpret_cast<const float4 *>(&bias[n0 + c + 4]);
    __half2 h2[4];
    h2[0] = __floats2half2_rn(tanhf(a0.x + vb0.x), tanhf(a0.y + vb0.y));
    h2[1] = __floats2half2_rn(tanhf(a0.z + vb0.z), tanhf(a0.w + vb0.w));
    h2[2] = __floats2half2_rn(tanhf(a1.x + vb1.x), tanhf(a1.y + vb1.y));
    h2[3] = __floats2half2_rn(tanhf(a1.z + vb1.z), tanhf(a1.w + vb1.w));
    const long base = (long)(m0 + row) * Hd + n0 + c;
    *reinterpret_cast<uint4 *>(&dh[base]) = *reinterpret_cast<uint4 *>(h2);
}

__device__ __forceinline__ void convert_w(
    const float *__restrict__ s, __half *d, int n, int gtid)
{
    for (int i = gtid; i < n; i += NCTA * NTHR) d[i] = __float2half(s[i]);
}

// Final-GEMM epilogue: out[:, s, :] tile = acc + fc_b.
__device__ __forceinline__ void final_store(
    const float (&acc)[4][4][4], float *__restrict__ out,
    const float *__restrict__ fc_b, int s, int m0, int n0)
{
    const int lid = threadIdx.x & 31, wid = threadIdx.x >> 5;
    const int wm = wid >> 2, wn = wid & 3;
    const int g = lid >> 2, t = lid & 3;
#pragma unroll
    for (int ma = 0; ma < 4; ++ma)
#pragma unroll
        for (int na = 0; na < 4; ++na) {
            const int row = m0 + wm * 64 + ma * 16 + g;
            const int col = n0 + wn * 32 + na * 8 + t * 2;
            const float bx = fc_b[col], by = fc_b[col + 1];
            *reinterpret_cast<float2 *>(
                &out[(long)row * (Tt * Ind) + (long)s * Ind + col]) =
                make_float2(acc[ma][na][0] + bx, acc[ma][na][1] + by);
            *reinterpret_cast<float2 *>(
                &out[(long)(row + 8) * (Tt * Ind) + (long)s * Ind + col]) =
                make_float2(acc[ma][na][2] + bx, acc[ma][na][3] + by);
        }
}

// M0 dump with global coords (phase 0b only; ldc = Hd).
__device__ __forceinline__ void dump_glob(
    const float (&acc)[4][4][4], float *__restrict__ dst, int m0, int n0)
{
    const int lid = threadIdx.x & 31, wid = threadIdx.x >> 5;
    const int wm = wid >> 2, wn = wid & 3;
    const int g = lid >> 2, t = lid & 3;
#pragma unroll
    for (int ma = 0; ma < 4; ++ma)
#pragma unroll
        for (int na = 0; na < 4; ++na) {
            const int row = m0 + wm * 64 + ma * 16 + g;
            const int col = n0 + wn * 32 + na * 8 + t * 2;
            *reinterpret_cast<float2 *>(&dst[(long)row * Hd + col]) =
                make_float2(acc[ma][na][0], acc[ma][na][1]);
            *reinterpret_cast<float2 *>(&dst[(long)(row + 8) * Hd + col]) =
                make_float2(acc[ma][na][2], acc[ma][na][3]);
        }
}

__global__ void __launch_bounds__(NTHR, 1) rnn_tc(
    const float *__restrict__ y0,
    const float *__restrict__ W_ih0, const float *__restrict__ W_hh0,
    const float *__restrict__ b_ih0, const float *__restrict__ b_hh0,
    const float *__restrict__ W_ih1, const float *__restrict__ W_hh1,
    const float *__restrict__ b_ih1, const float *__restrict__ b_hh1,
    const float *__restrict__ fc_W, const float *__restrict__ fc_b,
    float *__restrict__ out)
{
    extern __shared__ char smem[];
    const u32 sb = smem_u32(smem);
    const int tid = threadIdx.x, bid = blockIdx.x;
    const int gtid = bid * NTHR + tid;
    const int stride = NCTA * NTHR;

    // ---- phase 0a (every replay): weight converts, transpose, init, biases
    convert_w(W_ih0, g_Wih0, Hd * Ind, gtid);
    convert_w(W_hh0, g_Whh0, Hd * Hd, gtid);
    convert_w(W_ih1, g_Wih1, Hd * Hd, gtid);
    convert_w(W_hh1, g_Whh1, Hd * Hd, gtid);
    convert_w(fc_W, g_fcW, Ind * Hd, gtid);
    for (int i = gtid; i < Hd * Ind; i += stride) {  // fcWT[j][k] = fc_W[k][j]
        const int j = i >> 8, k = i & 255;
        g_fcWT[i] = __float2half(fc_W[(long)k * Hd + j]);
    }
    for (int i = gtid; i < Bm * Ind; i += stride) {
        const float v = y0[i];
        g_y[i] = __float2half(v);
        out[(long)(i >> 8) * (Tt * Ind) + (i & 255)] = v;  // out[:, 0, :]
    }
    for (int i = gtid; i < BmHd; i += stride) {
        const __half z = __float2half(0.0f);
        g_h0[0][i] = z;
        g_H1[i] = z;                       // history slot 0 = h1 initial state
    }
    for (int j = gtid; j < Hd; j += stride) {
        const float s1 = b_ih0[j] + b_hh0[j];
        g_biasA1[j] = s1;
        float a = 0.0f;
        const float *wr = &W_ih0[(long)j * Ind];
        for (int k = 0; k < Ind; ++k) a += wr[k] * fc_b[k];
        g_biasAf[j] = a + s1;              // fc_b @ W_ih0^T + b_ih0 + b_hh0
        g_biasB[j] = b_ih1[j] + b_hh1[j];
    }
    if (gtid < 16) g_tcnt[gtid] = 0;
    grid_sync();

    // ---- phase 0b: M0 = W_ih0 @ fc_W (1024x1024, K=256), 64 tiles x 2 k-splits
    {
        const int kk = bid >> 6, tj = bid & 63, tm = tj >> 3, tn = tj & 7;
        float acc[4][4][4] = {};
        gemm_pipe(acc, sb,
                  g_Wih0 + (long)tm * 128 * Ind, Ind,
                  g_fcWT + (long)tn * 128 * Ind, Ind,
                  kk * 128, 2);
        dump_glob(acc, &g_part[0] + (long)kk * Hd * Hd, tm * 128, tn * 128);
    }
    grid_sync();
    {   // M0 reduce -> single fp16
        const float *p0 = &g_part[0];
        const float *p1 = p0 + (long)Hd * Hd;
        for (int i = gtid * 4; i < Hd * Hd; i += stride * 4) {
            const float4 a = __ldcg(reinterpret_cast<const float4 *>(&p0[i]));
            const float4 b = __ldcg(reinterpret_cast<const float4 *>(&p1[i]));
            g_M0[i]     = __float2half(a.x + b.x);
            g_M0[i + 1] = __float2half(a.y + b.y);
            g_M0[i + 2] = __float2half(a.z + b.z);
            g_M0[i + 3] = __float2half(a.w + b.w);
        }
    }
    grid_sync();

    // tile mapping (R8/R14/R16): 8 k-splits x (2m x 8n) over [256, 1024]
    const int ksAB = bid >> 4;
    const int tile = bid & 15;
    const int m0AB = ((bid >> 3) & 1) * 128, n0AB = (bid & 7) * 128;
    float *tbase = g_part + (long)tile * 8 * TILE_F;
    float *mypart = tbase + ksAB * TILE_F;
    u32 expv = 0;

    for (int s = 1; s < Tt; ++s) {
        const int cb = (s - 1) & 1, nb = s & 1;
        const __half *h1p = g_H1 + (long)(s - 1) * BmHd;

        // ---- stage A: h0(s) = tanh(h1(s-1)@M0^T + h0(s-1)@Whh0^T + biasAf)
        {
            const int nprod = (s == 1) ? 4 : 8;
            const bool iproduce = (s == 1) ? (ksAB < 4) : true;
            if (iproduce) {
                float acc[4][4][4] = {};
                if (ksAB < 4) {
                    if (s == 1)
                        gemm_pipe(acc, sb,
                                  g_y + (long)m0AB * Ind, Ind,
                                  g_Wih0 + (long)n0AB * Ind, Ind,
                                  ksAB * 64, 1);
                    else
                        gemm_pipe(acc, sb,
                                  h1p + (long)m0AB * Hd, Hd,
                                  g_M0 + (long)n0AB * Hd, Hd,
                                  ksAB * 256, 4);
                } else {
                    gemm_pipe(acc, sb,
                              g_h0[cb] + (long)m0AB * Hd, Hd,
                              g_Whh0 + (long)n0AB * Hd, Hd,
                              (ksAB - 4) * 256, 4);
                }
                dump_loc(acc, mypart);
            }
            expv += (u32)nprod;
            tile_sync(tile, iproduce, expv);
            merge_h(tbase, ksAB, nprod, s == 1 ? g_biasA1 : g_biasAf,
                    m0AB, n0AB, g_h0[nb]);
        }
        grid_sync();

        // ---- stage B: h1(s) = tanh(h0(s)@Wih1^T + h1(s-1)@Whh1^T + biasB)
        {
            float acc[4][4][4] = {};
            if (ksAB < 4)
                gemm_pipe(acc, sb,
                          g_h0[nb] + (long)m0AB * Hd, Hd,
                          g_Wih1 + (long)n0AB * Hd, Hd,
                          ksAB * 256, 4);
            else
                gemm_pipe(acc, sb,
                          h1p + (long)m0AB * Hd, Hd,
                          g_Whh1 + (long)n0AB * Hd, Hd,
                          (ksAB - 4) * 256, 4);
            dump_loc(acc, mypart);
            expv += 8u;
            tile_sync(tile, true, expv);
            merge_h(tbase, ksAB, 8, g_biasB, m0AB, n0AB,
                    g_H1 + (long)s * BmHd);
        }
        grid_sync();
    }

    // ---- batched output GEMM: out[:, s, :] = H1[s] @ fc_W^T + fc_b, s = 1..511
    for (int job = bid; job < (Tt - 1) * 4; job += NCTA) {
        const int ntile = job & 1;
        const int rt = job >> 1;
        const int s = 1 + (rt >> 1);
        const int m0 = (rt & 1) * 128, n0 = ntile * 128;
        float acc[4][4][4] = {};
        gemm_pipe(acc, sb,
                  g_H1 + (long)s * BmHd + (long)m0 * Hd, Hd,
                  g_fcW + (long)n0 * Hd, Hd,
                  0, 16);
        final_store(acc, out, fc_b, s, m0, n0);
    }
}

extern "C" void kernel_launch(void *const *d_in, const int *in_sizes, int n_in,
                              void *d_out, int out_size) {
    (void)in_sizes; (void)n_in; (void)out_size;
    const float *y0    = (const float *)d_in[0];
    // d_in[1] = t (length only; unused)
    const float *W_ih0 = (const float *)d_in[2];
    const float *W_hh0 = (const float *)d_in[3];
    const float *b_ih0 = (const float *)d_in[4];
    const float *b_hh0 = (const float *)d_in[5];
    const float *W_ih1 = (const float *)d_in[6];
    const float *W_hh1 = (const float *)d_in[7];
    const float *b_ih1 = (const float *)d_in[8];
    const float *b_hh1 = (const float *)d_in[9];
    const float *fc_W  = (const float *)d_in[10];
    const float *fc_b  = (const float *)d_in[11];
    float *out = (float *)d_out;

    cudaFuncSetAttribute(rnn_tc, cudaFuncAttributeMaxDynamicSharedMemorySize, SMEM_BYTES);
    rnn_tc<<<NCTA, NTHR, SMEM_BYTES>>>(y0, W_ih0, W_hh0, b_ih0, b_hh0,
                                       W_ih1, W_hh1, b_ih1, b_hh1,
                                       fc_W, fc_b, out);
}